// round 15
// baseline (speedup 1.0000x reference)
#include <cuda_runtime.h>
#include <cuda_bf16.h>
#include <stdint.h>
#include <math.h>

#define NBT   32768     // B*T
#define HID   1024
#define G3    768       // 3*OUT
#define OUTD  256
#define TST   128
#define INF   128
#define BATCH 256

typedef unsigned long long ull;

// ---------------- device-global scratch (no allocations allowed) -----------
__device__ __align__(16) float d_gi[NBT * G3];     // hoisted input gates (hx GRU)
__device__ __align__(16) float d_gim[TST * G3];    // input gates (hm GRU)
__device__ float d_sum[HID];       // zero at load; re-zeroed by k_final
__device__ float d_sumsq[HID];
__device__ int   d_ctr;
__device__ __align__(16) float d_scale[HID];
__device__ __align__(16) float d_shift[HID];
__device__ __align__(16) float d_bip[G3];          // folded gi bias
// bf16 split operands for the tensor-core gi GEMM (e raw; W' = W*scale)
__device__ __align__(16) __nv_bfloat16 d_ehi[NBT * HID];
__device__ __align__(16) __nv_bfloat16 d_elo[NBT * HID];
__device__ __align__(16) __nv_bfloat16 d_whi[G3 * HID];
__device__ __align__(16) __nv_bfloat16 d_wlo[G3 * HID];
// plain k-major transposed scan weights: w[k*G3 + j]
__device__ __align__(16) float d_whh2x[OUTD * G3];
__device__ __align__(16) float d_whh2m[OUTD * G3];
__device__ __align__(16) float d_hxf[BATCH * OUTD];
__device__ __align__(16) float d_hmf[OUTD];

// ---------------- packed f32x2 helpers -------------------------------------
__device__ __forceinline__ ull pk2(float lo, float hi) {
    ull r; asm("mov.b64 %0,{%1,%2};" : "=l"(r) : "f"(lo), "f"(hi)); return r;
}
__device__ __forceinline__ void fma2(ull& d, ull a, ull b) {
    asm("fma.rn.f32x2 %0,%1,%2,%3;" : "=l"(d) : "l"(a), "l"(b), "l"(d));
}
__device__ __forceinline__ float2 upk2(ull v) {
    float2 f; asm("mov.b64 {%0,%1},%2;" : "=f"(f.x), "=f"(f.y) : "l"(v)); return f;
}
__device__ __forceinline__ float fsig(float x) { return 1.0f / (1.0f + __expf(-x)); }
__device__ __forceinline__ float ftanh(float x) { return 2.0f / (1.0f + __expf(-2.0f * x)) - 1.0f; }

// ---------------- HMMA m16n8k16 bf16 + ldmatrix + cp.async (baseline PTX) --
__device__ __forceinline__ void mma16816(float* d, const unsigned int* a,
                                         const unsigned int* b) {
    asm volatile(
        "mma.sync.aligned.m16n8k16.row.col.f32.bf16.bf16.f32 "
        "{%0,%1,%2,%3}, {%4,%5,%6,%7}, {%8,%9}, {%0,%1,%2,%3};"
        : "+f"(d[0]), "+f"(d[1]), "+f"(d[2]), "+f"(d[3])
        : "r"(a[0]), "r"(a[1]), "r"(a[2]), "r"(a[3]), "r"(b[0]), "r"(b[1]));
}
__device__ __forceinline__ void ldsm4(unsigned int* r, unsigned int saddr) {
    asm volatile(
        "ldmatrix.sync.aligned.m8n8.x4.shared.b16 {%0,%1,%2,%3}, [%4];"
        : "=r"(r[0]), "=r"(r[1]), "=r"(r[2]), "=r"(r[3]) : "r"(saddr));
}
__device__ __forceinline__ void cpasync16(unsigned int saddr, const void* gaddr) {
    asm volatile("cp.async.cg.shared.global [%0], [%1], 16;"
                 :: "r"(saddr), "l"(gaddr));
}
#define CP_COMMIT() asm volatile("cp.async.commit_group;" ::: "memory")
#define CP_WAIT(n)  asm volatile("cp.async.wait_group %0;" :: "n"(n) : "memory")

__device__ __forceinline__ unsigned int smem_to_u32(const void* smem_ptr) {
    unsigned int addr;
    asm("{ .reg .u64 tmp; cvta.to.shared.u64 tmp, %1; cvt.u32.u64 %0, tmp; }"
        : "=r"(addr) : "l"(smem_ptr));
    return addr;
}

// ---------------- k_embed: e = leaky(x@W^T+b); raw-e bf16 split out; -------
// BN stats + finalize. M=32768, N=1024, K=128. Tile 128x128, 256 threads.
__global__ void __launch_bounds__(256)
k_embed(const float* __restrict__ A, const float* __restrict__ B,
        const float* __restrict__ bias,
        const float* __restrict__ gamma, const float* __restrict__ beta) {
    __shared__ __align__(16) float As[16][132];
    __shared__ __align__(16) float Bs[16][132];
    const int m0 = blockIdx.x * 128, n0 = blockIdx.y * 128;
    const int tid = threadIdx.x, tx = tid & 15, ty = tid >> 4;
    const int r0 = tid >> 2, qa = tid & 3, r1 = r0 + 64;

    ull acc[8][4];
#pragma unroll
    for (int i = 0; i < 8; i++) {
#pragma unroll
        for (int j = 0; j < 4; j++) { acc[i][j] = 0ull; }
    }

    const float* pa0 = &A[(size_t)(m0 + r0) * INF + qa * 4];
    const float* pa1 = &A[(size_t)(m0 + r1) * INF + qa * 4];
    const float* pb0 = &B[(size_t)(n0 + r0) * INF + qa * 4];
    const float* pb1 = &B[(size_t)(n0 + r1) * INF + qa * 4];

    float4 ra0 = *(const float4*)pa0;
    float4 ra1 = *(const float4*)pa1;
    float4 rb0 = *(const float4*)pb0;
    float4 rb1 = *(const float4*)pb1;

    const int NC = INF / 16;
    for (int kt = 0; kt < NC; kt++) {
        As[qa * 4 + 0][r0] = ra0.x; As[qa * 4 + 1][r0] = ra0.y;
        As[qa * 4 + 2][r0] = ra0.z; As[qa * 4 + 3][r0] = ra0.w;
        As[qa * 4 + 0][r1] = ra1.x; As[qa * 4 + 1][r1] = ra1.y;
        As[qa * 4 + 2][r1] = ra1.z; As[qa * 4 + 3][r1] = ra1.w;
        Bs[qa * 4 + 0][r0] = rb0.x; Bs[qa * 4 + 1][r0] = rb0.y;
        Bs[qa * 4 + 2][r0] = rb0.z; Bs[qa * 4 + 3][r0] = rb0.w;
        Bs[qa * 4 + 0][r1] = rb1.x; Bs[qa * 4 + 1][r1] = rb1.y;
        Bs[qa * 4 + 2][r1] = rb1.z; Bs[qa * 4 + 3][r1] = rb1.w;
        __syncthreads();
        if (kt + 1 < NC) {
            const int ko = (kt + 1) * 16;
            ra0 = *(const float4*)(pa0 + ko);
            ra1 = *(const float4*)(pa1 + ko);
            rb0 = *(const float4*)(pb0 + ko);
            rb1 = *(const float4*)(pb1 + ko);
        }
#pragma unroll 4
        for (int k = 0; k < 16; k++) {
            float4 af0 = *(const float4*)&As[k][ty * 8];
            float4 af1 = *(const float4*)&As[k][ty * 8 + 4];
            ulonglong2 b01 = *(const ulonglong2*)&Bs[k][tx * 8];
            ulonglong2 b23 = *(const ulonglong2*)&Bs[k][tx * 8 + 4];
            float av[8];
            av[0] = af0.x; av[1] = af0.y; av[2] = af0.z; av[3] = af0.w;
            av[4] = af1.x; av[5] = af1.y; av[6] = af1.z; av[7] = af1.w;
#pragma unroll
            for (int i = 0; i < 8; i++) {
                ull ap = pk2(av[i], av[i]);
                fma2(acc[i][0], ap, b01.x);
                fma2(acc[i][1], ap, b01.y);
                fma2(acc[i][2], ap, b23.x);
                fma2(acc[i][3], ap, b23.y);
            }
        }
        __syncthreads();
    }

    float bv[8];
#pragma unroll
    for (int c = 0; c < 8; c++) { bv[c] = bias[n0 + tx * 8 + c]; }

    float ssum[8], ssq[8];
#pragma unroll
    for (int c = 0; c < 8; c++) { ssum[c] = 0.0f; ssq[c] = 0.0f; }
#pragma unroll
    for (int i = 0; i < 8; i++) {
        const int m = m0 + ty * 8 + i;
        __nv_bfloat16 hh[8];
        __nv_bfloat16 ll[8];
#pragma unroll
        for (int jj = 0; jj < 4; jj++) {
            float2 v = upk2(acc[i][jj]);
            const int c0 = jj * 2, c1 = jj * 2 + 1;
            float v0 = v.x + bv[c0]; v0 = (v0 >= 0.0f) ? v0 : 0.2f * v0;
            float v1 = v.y + bv[c1]; v1 = (v1 >= 0.0f) ? v1 : 0.2f * v1;
            ssum[c0] += v0; ssq[c0] += v0 * v0;
            ssum[c1] += v1; ssq[c1] += v1 * v1;
            hh[c0] = __float2bfloat16(v0);
            ll[c0] = __float2bfloat16(v0 - __bfloat162float(hh[c0]));
            hh[c1] = __float2bfloat16(v1);
            ll[c1] = __float2bfloat16(v1 - __bfloat162float(hh[c1]));
        }
        *(uint4*)&d_ehi[(size_t)m * HID + n0 + tx * 8] = *(uint4*)hh;
        *(uint4*)&d_elo[(size_t)m * HID + n0 + tx * 8] = *(uint4*)ll;
    }
    float* sb = (float*)As;
    __syncthreads();
#pragma unroll
    for (int c = 0; c < 8; c++) { sb[ty * 128 + tx * 8 + c] = ssum[c]; }
    __syncthreads();
    if (tid < 128) {
        float tot = 0.0f;
#pragma unroll
        for (int rr = 0; rr < 16; rr++) { tot += sb[rr * 128 + tid]; }
        atomicAdd(&d_sum[n0 + tid], tot);
    }
    __syncthreads();
#pragma unroll
    for (int c = 0; c < 8; c++) { sb[ty * 128 + tx * 8 + c] = ssq[c]; }
    __syncthreads();
    if (tid < 128) {
        float tot = 0.0f;
#pragma unroll
        for (int rr = 0; rr < 16; rr++) { tot += sb[rr * 128 + tid]; }
        atomicAdd(&d_sumsq[n0 + tid], tot);
    }
    __threadfence();
    __syncthreads();
    __shared__ int last;
    if (tid == 0) {
        int v = atomicAdd(&d_ctr, 1);
        last = (v == (int)(gridDim.x * gridDim.y) - 1) ? 1 : 0;
    }
    __syncthreads();
    if (last) {
        __threadfence();
        for (int h = tid; h < HID; h += 256) {
            float mean = d_sum[h] * (1.0f / 32768.0f);
            float var = d_sumsq[h] * (1.0f / 32768.0f) - mean * mean;
            var = var > 0.0f ? var : 0.0f;
            float sc = gamma[h] * rsqrtf(var + 1e-5f);
            d_scale[h] = sc;
            d_shift[h] = beta[h] - mean * sc;
        }
    }
}

// ---------------- k_prep: whh plain transposes + gim + BN-folded W'/bias' --
__global__ void k_prep(const float* __restrict__ wx, const float* __restrict__ wm,
                       const float* __restrict__ mem, const float* __restrict__ wim,
                       const float* __restrict__ bim,
                       const float* __restrict__ wih, const float* __restrict__ bih) {
    const int blk = blockIdx.x, tid = threadIdx.x;
    if (blk < 768) {
        const int idx = blk * 256 + tid;
        const int j = idx / OUTD, k = idx % OUTD;
        const int dst = k * G3 + j;     // plain k-major transpose
        d_whh2x[dst] = wx[idx];
        d_whh2m[dst] = wm[idx];
    } else if (blk < 896) {
        const int t = blk - 768;
        const float4* m4 = (const float4*)(mem + t * HID);
        for (int j = tid; j < G3; j += 256) {
            const float4* w4 = (const float4*)(wim + (size_t)j * HID);
            float acc = bim[j];
#pragma unroll 8
            for (int k = 0; k < HID / 4; k++) {
                float4 a = m4[k], b = w4[k];
                acc = fmaf(a.x, b.x, fmaf(a.y, b.y, fmaf(a.z, b.z, fmaf(a.w, b.w, acc))));
            }
            d_gim[t * G3 + j] = acc;
        }
    } else {
        // W'[j,:] = wih[j,:]*scale;  bias'[j] = bih[j] + dot(shift, wih[j,:])
        const int j = blk - 896;
        const float* wr = wih + (size_t)j * HID;
        const int h0 = tid * 4;
        float4 w4 = *(const float4*)&wr[h0];
        float4 sc = *(const float4*)&d_scale[h0];
        float4 sh = *(const float4*)&d_shift[h0];
        float wv[4];
        wv[0] = w4.x * sc.x; wv[1] = w4.y * sc.y;
        wv[2] = w4.z * sc.z; wv[3] = w4.w * sc.w;
        float dot = w4.x * sh.x + w4.y * sh.y + w4.z * sh.z + w4.w * sh.w;
        __nv_bfloat16 hh[4];
        __nv_bfloat16 ll[4];
#pragma unroll
        for (int q = 0; q < 4; q++) {
            hh[q] = __float2bfloat16(wv[q]);
            ll[q] = __float2bfloat16(wv[q] - __bfloat162float(hh[q]));
        }
        *(ull*)&d_whi[(size_t)j * HID + h0] = *(ull*)hh;
        *(ull*)&d_wlo[(size_t)j * HID + h0] = *(ull*)ll;
        __shared__ float red[256];
        red[tid] = dot;
        __syncthreads();
        for (int s = 128; s > 0; s >>= 1) {
            if (tid < s) { red[tid] += red[tid + s]; }
            __syncthreads();
        }
        if (tid == 0) { d_bip[j] = bih[j] + red[0]; }
    }
}

// ---------------- k_gemm_mma: gi = split-bf16 HMMA GEMM + bias' ------------
#define PITCH 72
#define BUFE  (128 * PITCH)

__global__ void __launch_bounds__(128, 2)
k_gemm_mma(const float* __restrict__ bias) {
    extern __shared__ __nv_bfloat16 sm[];
    const int tid = threadIdx.x;
    const int wid = tid >> 5, lane = tid & 31;
    const int m0 = blockIdx.x * 128, n0 = blockIdx.y * 128;
    const int wm = (wid >> 1) * 64, wn = (wid & 1) * 64;
    const int g = lane >> 2, tig = lane & 3;
    const unsigned int sbase = smem_to_u32(sm);

    const int a_row_off = (lane & 7) + ((lane >> 3) & 1) * 8;
    const int a_col_off = (lane >> 4) * 8;
    const int b_row_off = (lane & 7) + (lane >> 4) * 8;
    const int b_col_off = ((lane >> 3) & 1) * 8;

    float acc[4][8][4];
#pragma unroll
    for (int mt = 0; mt < 4; mt++)
#pragma unroll
        for (int nt = 0; nt < 8; nt++)
#pragma unroll
            for (int r = 0; r < 4; r++) { acc[mt][nt][r] = 0.0f; }

    auto stage = [&](int c, int buf) {
        const __nv_bfloat16* Ap = (c < 32) ? d_ehi : d_elo;
        const __nv_bfloat16* Bp = (c < 16) ? d_whi : ((c < 32) ? d_wlo : d_whi);
        const int kk = (c & 15) * 64;
        const unsigned int ab = sbase + (unsigned int)(buf * 2 * BUFE) * 2u;
        const unsigned int bb = ab + (unsigned int)BUFE * 2u;
#pragma unroll
        for (int it = 0; it < 8; it++) {
            const int idx = tid + it * 128;
            const int row = idx >> 3;
            const int col = (idx & 7) * 8;
            cpasync16(ab + (unsigned int)(row * PITCH + col) * 2u,
                      Ap + (size_t)(m0 + row) * HID + kk + col);
            cpasync16(bb + (unsigned int)(row * PITCH + col) * 2u,
                      Bp + (size_t)(n0 + row) * HID + kk + col);
        }
        CP_COMMIT();
    };

    stage(0, 0);
    for (int c = 0; c < 48; c++) {
        const int buf = c & 1;
        if (c + 1 < 48) {
            stage(c + 1, 1 - buf);
            CP_WAIT(1);
        } else {
            CP_WAIT(0);
        }
        __syncthreads();
        const unsigned int ab = sbase + (unsigned int)(buf * 2 * BUFE) * 2u;
        const unsigned int bb = ab + (unsigned int)BUFE * 2u;
#pragma unroll
        for (int ks = 0; ks < 4; ks++) {
            const int kw = ks * 16;
            unsigned int afr[4][4];
#pragma unroll
            for (int mt = 0; mt < 4; mt++) {
                ldsm4(afr[mt], ab + (unsigned int)((wm + mt * 16 + a_row_off) * PITCH
                                                   + kw + a_col_off) * 2u);
            }
            unsigned int bfr[8][2];
#pragma unroll
            for (int p = 0; p < 4; p++) {
                unsigned int tmp[4];
                ldsm4(tmp, bb + (unsigned int)((wn + p * 16 + b_row_off) * PITCH
                                               + kw + b_col_off) * 2u);
                bfr[2 * p][0] = tmp[0]; bfr[2 * p][1] = tmp[1];
                bfr[2 * p + 1][0] = tmp[2]; bfr[2 * p + 1][1] = tmp[3];
            }
#pragma unroll
            for (int mt = 0; mt < 4; mt++)
#pragma unroll
                for (int nt = 0; nt < 8; nt++) { mma16816(acc[mt][nt], afr[mt], bfr[nt]); }
        }
        __syncthreads();
    }

#pragma unroll
    for (int mt = 0; mt < 4; mt++) {
        const int row = m0 + wm + mt * 16 + g;
#pragma unroll
        for (int nt = 0; nt < 8; nt++) {
            const int col = n0 + wn + nt * 8 + tig * 2;
            const float b0 = bias[col], b1 = bias[col + 1];
            float2 v0, v1;
            v0.x = acc[mt][nt][0] + b0; v0.y = acc[mt][nt][1] + b1;
            v1.x = acc[mt][nt][2] + b0; v1.y = acc[mt][nt][3] + b1;
            *(float2*)&d_gi[(size_t)row * G3 + col] = v0;
            *(float2*)&d_gi[(size_t)(row + 8) * G3 + col] = v1;
        }
    }
}

// ---------------- k_scan: GRU recurrences, j-packed accumulators -----------
// 384 threads: thread (p = tid&1, jq = tid>>1) computes gates j0..j0+3 for
// batch pair p (rows 2p, 2p+1). Weights load straight into fma2 operands
// (j-adjacent packing); h broadcast is 2x LDS.64 per k2 (8B each).
__global__ void __launch_bounds__(384, 1)
k_scan(const float* __restrict__ bhhx, const float* __restrict__ bhhm) {
    __shared__ __align__(16) float h32[OUTD * 4];   // h[k][b], b = 0..3
    __shared__ __align__(16) float ghs[4 * G3];     // gates per batch row
    const int tid = threadIdx.x;

    if (blockIdx.x < 64) {
        const int bb = blockIdx.x * 4;
        const int p = tid & 1, jq = tid >> 1, j0 = jq * 4;
        for (int i = tid; i < OUTD * 4; i += 384) { h32[i] = 0.0f; }
        const float4 b4 = *(const float4*)&bhhx[j0];
        const ull bj0 = pk2(b4.x, b4.y);   // (bias_j0, bias_j1)
        const ull bj1 = pk2(b4.z, b4.w);   // (bias_j2, bias_j3)
        const int d = tid;                 // update dim (tid < 256)
        __syncthreads();
        for (int t = 0; t < TST; t++) {
            float gr[4], gz[4], gn[4];
            if (tid < OUTD) {
#pragma unroll
                for (int b = 0; b < 4; b++) {
                    const float* gi = &d_gi[((size_t)(bb + b) * TST + t) * G3];
                    gr[b] = gi[d]; gz[b] = gi[OUTD + d]; gn[b] = gi[2 * OUTD + d];
                }
            }
            ull a00 = bj0, a10 = bj1;      // batch 2p:   (j0,j1), (j2,j3)
            ull a01 = bj0, a11 = bj1;      // batch 2p+1
#pragma unroll 8
            for (int k2 = 0; k2 < OUTD / 2; k2++) {
                const int k0 = 2 * k2;
                const float2 hb0 = *(const float2*)&h32[k0 * 4 + 2 * p];
                const float2 hb1 = *(const float2*)&h32[(k0 + 1) * 4 + 2 * p];
                const ulonglong2 w0 = *(const ulonglong2*)&d_whh2x[k0 * G3 + j0];
                const ulonglong2 w1 = *(const ulonglong2*)&d_whh2x[(k0 + 1) * G3 + j0];
                ull h;
                h = pk2(hb0.x, hb0.x); fma2(a00, h, w0.x); fma2(a10, h, w0.y);
                h = pk2(hb0.y, hb0.y); fma2(a01, h, w0.x); fma2(a11, h, w0.y);
                h = pk2(hb1.x, hb1.x); fma2(a00, h, w1.x); fma2(a10, h, w1.y);
                h = pk2(hb1.y, hb1.y); fma2(a01, h, w1.x); fma2(a11, h, w1.y);
            }
            ulonglong2 s0; s0.x = a00; s0.y = a10;
            ulonglong2 s1; s1.x = a01; s1.y = a11;
            *(ulonglong2*)&ghs[(2 * p) * G3 + j0] = s0;
            *(ulonglong2*)&ghs[(2 * p + 1) * G3 + j0] = s1;
            __syncthreads();
            if (tid < OUTD) {
                float hn[4];
                const float4 hold = *(const float4*)&h32[d * 4];
                const float ho[4] = {hold.x, hold.y, hold.z, hold.w};
#pragma unroll
                for (int b = 0; b < 4; b++) {
                    float r = fsig(gr[b] + ghs[b * G3 + d]);
                    float z = fsig(gz[b] + ghs[b * G3 + OUTD + d]);
                    float n = ftanh(gn[b] + r * ghs[b * G3 + 2 * OUTD + d]);
                    hn[b] = (1.0f - z) * n + z * ho[b];
                }
                *(float4*)&h32[d * 4] = *(float4*)hn;
            }
            __syncthreads();
        }
        if (tid < OUTD) {
#pragma unroll
            for (int b = 0; b < 4; b++) {
                d_hxf[(bb + b) * OUTD + tid] = h32[tid * 4 + b];
            }
        }
    } else {
        // hm chain: single batch-invariant recurrence
        float* hm_s = h32;       // reuse (256 floats)
        float* ghm_s = ghs;      // reuse (768 floats)
        const int j0 = 2 * tid;
        for (int i = tid; i < OUTD; i += 384) { hm_s[i] = 0.0f; }
        const float2 bh2 = *(const float2*)&bhhm[j0];
        __syncthreads();
        for (int t = 0; t < TST; t++) {
            float grv = 0, gzv = 0, gnv = 0;
            if (tid < OUTD) {
                const float* gi = &d_gim[t * G3];
                grv = gi[tid]; gzv = gi[OUTD + tid]; gnv = gi[2 * OUTD + tid];
            }
            float a0 = bh2.x, a1 = bh2.y;
#pragma unroll 16
            for (int k = 0; k < OUTD; k++) {
                const float2 w2 = *(const float2*)&d_whh2m[k * G3 + j0];
                const float hk = hm_s[k];
                a0 = fmaf(hk, w2.x, a0);
                a1 = fmaf(hk, w2.y, a1);
            }
            ghm_s[j0] = a0; ghm_s[j0 + 1] = a1;
            __syncthreads();
            if (tid < OUTD) {
                float rr = fsig(grv + ghm_s[tid]);
                float zz = fsig(gzv + ghm_s[OUTD + tid]);
                float nn = ftanh(gnv + rr * ghm_s[2 * OUTD + tid]);
                hm_s[tid] = (1.0f - zz) * nn + zz * hm_s[tid];
            }
            __syncthreads();
        }
        for (int dd = tid; dd < OUTD; dd += 384) { d_hmf[dd] = hm_s[dd]; }
    }
}

// ---------------- k_final: cosine gate + blend + stat cleanup --------------
__global__ void k_final(const float* __restrict__ Wsx, const float* __restrict__ bsx,
                        const float* __restrict__ Wsm, const float* __restrict__ bsm,
                        float* __restrict__ out) {
    const int b = blockIdx.x, lane = threadIdx.x;
    const int gidx = b * 32 + lane;
    if (gidx < HID) { d_sum[gidx] = 0.0f; d_sumsq[gidx] = 0.0f; }
    if (gidx == 0) { d_ctr = 0; }

    float hx[8], hm[8];
#pragma unroll
    for (int i = 0; i < 8; i++) {
        hx[i] = d_hxf[b * OUTD + lane * 8 + i];
        hm[i] = d_hmf[lane * 8 + i];
    }
    float qx[4], qm[4];
#pragma unroll
    for (int s = 0; s < 4; s++) {
        float ax = 0.0f, am = 0.0f;
#pragma unroll
        for (int i = 0; i < 8; i++) {
            ax = fmaf(hx[i], Wsx[s * OUTD + lane * 8 + i], ax);
            am = fmaf(hm[i], Wsm[s * OUTD + lane * 8 + i], am);
        }
        for (int off = 16; off; off >>= 1) {
            ax += __shfl_xor_sync(0xFFFFFFFFu, ax, off);
            am += __shfl_xor_sync(0xFFFFFFFFu, am, off);
        }
        qx[s] = ax + bsx[s];
        qm[s] = am + bsm[s];
    }
    float num = 0.0f, nx = 0.0f, nm = 0.0f;
#pragma unroll
    for (int s = 0; s < 4; s++) {
        num = fmaf(qx[s], qm[s], num);
        nx = fmaf(qx[s], qx[s], nx);
        nm = fmaf(qm[s], qm[s], nm);
    }
    float den = fmaxf(sqrtf(nx), 1e-8f) * fmaxf(sqrtf(nm), 1e-8f);
    float gg = 1.0f / (1.0f + expf(-num / den));
#pragma unroll
    for (int i = 0; i < 8; i++) {
        out[b * OUTD + lane * 8 + i] = gg * hx[i] + (1.0f - gg) * hm[i];
    }
}

// ---------------- launcher -------------------------------------------------
// Launch #4 = k_scan (ncu-profiled slot).
extern "C" void kernel_launch(void* const* d_in, const int* in_sizes, int n_in,
                              void* d_out, int out_size) {
    const float* x      = (const float*)d_in[0];
    const float* W_emb  = (const float*)d_in[1];
    const float* b_emb  = (const float*)d_in[2];
    const float* gamma  = (const float*)d_in[3];
    const float* beta   = (const float*)d_in[4];
    const float* memory = (const float*)d_in[5];
    const float* w_ih_x = (const float*)d_in[6];
    const float* w_hh_x = (const float*)d_in[7];
    const float* b_ih_x = (const float*)d_in[8];
    const float* b_hh_x = (const float*)d_in[9];
    const float* w_ih_m = (const float*)d_in[10];
    const float* w_hh_m = (const float*)d_in[11];
    const float* b_ih_m = (const float*)d_in[12];
    const float* b_hh_m = (const float*)d_in[13];
    const float* W_sx   = (const float*)d_in[14];
    const float* b_sx   = (const float*)d_in[15];
    const float* W_sm   = (const float*)d_in[16];
    const float* b_sm   = (const float*)d_in[17];
    float* out = (float*)d_out;

    float* bip = nullptr; cudaGetSymbolAddress((void**)&bip, d_bip);

    const int smem_mma = 2 * 2 * BUFE * (int)sizeof(__nv_bfloat16);  // 73728 B
    static int attr_set = 0;
    if (!attr_set) {
        cudaFuncSetAttribute(k_gemm_mma, cudaFuncAttributeMaxDynamicSharedMemorySize,
                             smem_mma);
        attr_set = 1;
    }

    // 1: embed GEMM + leaky + raw-e bf16 split + BN stats + finalize
    k_embed<<<dim3(256, 8), 256>>>(x, W_emb, b_emb, gamma, beta);
    // 2: prep (whh plain transpose + gim + BN-folded W' split + bias')
    k_prep<<<1664, 256>>>(w_hh_x, w_hh_m, memory, w_ih_m, b_ih_m, w_ih_x, b_ih_x);
    // 3: HMMA gi GEMM
    k_gemm_mma<<<dim3(256, 6), 128, smem_mma>>>(bip);
    // 4: recurrences (ncu-profiled slot)
    k_scan<<<65, 384>>>(b_hh_x, b_hh_m);
    // 5: gate + blend + stat cleanup
    k_final<<<256, 32>>>(W_sx, b_sx, W_sm, b_sm, out);
}

// round 16
// speedup vs baseline: 1.2343x; 1.2343x over previous
#include <cuda_runtime.h>
#include <cuda_bf16.h>
#include <stdint.h>
#include <math.h>

#define NBT   32768     // B*T
#define HID   1024
#define G3    768       // 3*OUT
#define OUTD  256
#define TST   128
#define INF   128
#define BATCH 256

typedef unsigned long long ull;

// ---------------- device-global scratch (no allocations allowed) -----------
__device__ __align__(16) float d_gi[NBT * G3];     // hoisted input gates (hx GRU)
__device__ __align__(16) float d_gim[TST * G3];    // input gates (hm GRU)
__device__ float d_sum[HID];       // zero at load; re-zeroed by k_final
__device__ float d_sumsq[HID];
__device__ int   d_ctr;
__device__ __align__(16) float d_scale[HID];
__device__ __align__(16) float d_shift[HID];
__device__ __align__(16) float d_bip[G3];          // folded gi bias
// bf16 hi/lo splits
__device__ __align__(16) __nv_bfloat16 d_xhi[NBT * INF];
__device__ __align__(16) __nv_bfloat16 d_xlo[NBT * INF];
__device__ __align__(16) __nv_bfloat16 d_wehi[HID * INF];
__device__ __align__(16) __nv_bfloat16 d_welo[HID * INF];
__device__ __align__(16) __nv_bfloat16 d_ehi[NBT * HID];
__device__ __align__(16) __nv_bfloat16 d_elo[NBT * HID];
__device__ __align__(16) __nv_bfloat16 d_whi[G3 * HID];
__device__ __align__(16) __nv_bfloat16 d_wlo[G3 * HID];
// interleaved 2k x 2j scan weights: w2[((k>>1)*G3 + j)*2 + (k&1)] = w[j][k]
__device__ __align__(16) float d_whh2x[OUTD * G3];
__device__ __align__(16) float d_whh2m[OUTD * G3];
__device__ __align__(16) float d_hxf[BATCH * OUTD];
__device__ __align__(16) float d_hmf[OUTD];

// ---------------- packed f32x2 helpers -------------------------------------
__device__ __forceinline__ ull pk2(float lo, float hi) {
    ull r; asm("mov.b64 %0,{%1,%2};" : "=l"(r) : "f"(lo), "f"(hi)); return r;
}
__device__ __forceinline__ void fma2(ull& d, ull a, ull b) {
    asm("fma.rn.f32x2 %0,%1,%2,%3;" : "=l"(d) : "l"(a), "l"(b), "l"(d));
}
__device__ __forceinline__ float2 upk2(ull v) {
    float2 f; asm("mov.b64 {%0,%1},%2;" : "=f"(f.x), "=f"(f.y) : "l"(v)); return f;
}
__device__ __forceinline__ float fsig(float x) { return 1.0f / (1.0f + __expf(-x)); }
__device__ __forceinline__ float ftanh(float x) { return 2.0f / (1.0f + __expf(-2.0f * x)) - 1.0f; }

// ---------------- HMMA m16n8k16 bf16 + ldmatrix + cp.async (baseline PTX) --
__device__ __forceinline__ void mma16816(float* d, const unsigned int* a,
                                         const unsigned int* b) {
    asm volatile(
        "mma.sync.aligned.m16n8k16.row.col.f32.bf16.bf16.f32 "
        "{%0,%1,%2,%3}, {%4,%5,%6,%7}, {%8,%9}, {%0,%1,%2,%3};"
        : "+f"(d[0]), "+f"(d[1]), "+f"(d[2]), "+f"(d[3])
        : "r"(a[0]), "r"(a[1]), "r"(a[2]), "r"(a[3]), "r"(b[0]), "r"(b[1]));
}
__device__ __forceinline__ void ldsm4(unsigned int* r, unsigned int saddr) {
    asm volatile(
        "ldmatrix.sync.aligned.m8n8.x4.shared.b16 {%0,%1,%2,%3}, [%4];"
        : "=r"(r[0]), "=r"(r[1]), "=r"(r[2]), "=r"(r[3]) : "r"(saddr));
}
__device__ __forceinline__ void cpasync16(unsigned int saddr, const void* gaddr) {
    asm volatile("cp.async.cg.shared.global [%0], [%1], 16;"
                 :: "r"(saddr), "l"(gaddr));
}
#define CP_COMMIT() asm volatile("cp.async.commit_group;" ::: "memory")
#define CP_WAIT(n)  asm volatile("cp.async.wait_group %0;" :: "n"(n) : "memory")

__device__ __forceinline__ unsigned int smem_to_u32(const void* smem_ptr) {
    unsigned int addr;
    asm("{ .reg .u64 tmp; cvta.to.shared.u64 tmp, %1; cvt.u32.u64 %0, tmp; }"
        : "=r"(addr) : "l"(smem_ptr));
    return addr;
}
__device__ __forceinline__ void bfsplit(float v, __nv_bfloat16& h, __nv_bfloat16& l) {
    h = __float2bfloat16(v);
    l = __float2bfloat16(v - __bfloat162float(h));
}

// ---------------- k_xsplit: bf16 hi/lo of x and W_emb ----------------------
// blocks [0,2048): x (2048 elems each); [2048,2112): W_emb.
__global__ void k_xsplit(const float* __restrict__ x, const float* __restrict__ wemb) {
    const int tid = threadIdx.x;
    const float* src;
    __nv_bfloat16 *dhi, *dlo;
    size_t base;
    if (blockIdx.x < 2048) {
        base = (size_t)blockIdx.x * 2048 + (size_t)tid * 8;
        src = x; dhi = d_xhi; dlo = d_xlo;
    } else {
        base = (size_t)(blockIdx.x - 2048) * 2048 + (size_t)tid * 8;
        src = wemb; dhi = d_wehi; dlo = d_welo;
    }
    float4 v0 = *(const float4*)&src[base];
    float4 v1 = *(const float4*)&src[base + 4];
    float v[8];
    v[0] = v0.x; v[1] = v0.y; v[2] = v0.z; v[3] = v0.w;
    v[4] = v1.x; v[5] = v1.y; v[6] = v1.z; v[7] = v1.w;
    __nv_bfloat16 hh[8];
    __nv_bfloat16 ll[8];
#pragma unroll
    for (int i = 0; i < 8; i++) { bfsplit(v[i], hh[i], ll[i]); }
    *(uint4*)&dhi[base] = *(uint4*)hh;
    *(uint4*)&dlo[base] = *(uint4*)ll;
}

// ---------------- k_embed_mma: e = leaky(x@W_emb^T + b), HMMA split-bf16 ---
// Tile 128x128, 4 warps of 64x64. K=128 -> 6 chunks (hi*hi x2, hi*lo x2,
// lo*hi x2). Epilogue: bias+leaky -> smem tile -> bf16 split + BN stats.
#define PITCH 72
#define BUFE  (128 * PITCH)
#define EPITCH 132

__global__ void __launch_bounds__(128, 2)
k_embed_mma(const float* __restrict__ bias,
            const float* __restrict__ gamma, const float* __restrict__ beta) {
    extern __shared__ __nv_bfloat16 sm[];
    const int tid = threadIdx.x;
    const int wid = tid >> 5, lane = tid & 31;
    const int m0 = blockIdx.x * 128, n0 = blockIdx.y * 128;
    const int wm = (wid >> 1) * 64, wn = (wid & 1) * 64;
    const int g = lane >> 2, tig = lane & 3;
    const unsigned int sbase = smem_to_u32(sm);

    const int a_row_off = (lane & 7) + ((lane >> 3) & 1) * 8;
    const int a_col_off = (lane >> 4) * 8;
    const int b_row_off = (lane & 7) + (lane >> 4) * 8;
    const int b_col_off = ((lane >> 3) & 1) * 8;

    float acc[4][8][4];
#pragma unroll
    for (int mt = 0; mt < 4; mt++)
#pragma unroll
        for (int nt = 0; nt < 8; nt++)
#pragma unroll
            for (int r = 0; r < 4; r++) { acc[mt][nt][r] = 0.0f; }

    auto stage = [&](int c, int buf) {
        const __nv_bfloat16* Ap = (c < 4) ? d_xhi : d_xlo;
        const __nv_bfloat16* Bp = (c < 2) ? d_wehi : ((c < 4) ? d_welo : d_wehi);
        const int kk = (c & 1) * 64;
        const unsigned int ab = sbase + (unsigned int)(buf * 2 * BUFE) * 2u;
        const unsigned int bb = ab + (unsigned int)BUFE * 2u;
#pragma unroll
        for (int it = 0; it < 8; it++) {
            const int idx = tid + it * 128;
            const int row = idx >> 3;
            const int col = (idx & 7) * 8;
            cpasync16(ab + (unsigned int)(row * PITCH + col) * 2u,
                      Ap + (size_t)(m0 + row) * INF + kk + col);
            cpasync16(bb + (unsigned int)(row * PITCH + col) * 2u,
                      Bp + (size_t)(n0 + row) * INF + kk + col);
        }
        CP_COMMIT();
    };

    stage(0, 0);
    for (int c = 0; c < 6; c++) {
        const int buf = c & 1;
        if (c + 1 < 6) {
            stage(c + 1, 1 - buf);
            CP_WAIT(1);
        } else {
            CP_WAIT(0);
        }
        __syncthreads();
        const unsigned int ab = sbase + (unsigned int)(buf * 2 * BUFE) * 2u;
        const unsigned int bb = ab + (unsigned int)BUFE * 2u;
#pragma unroll
        for (int ks = 0; ks < 4; ks++) {
            const int kw = ks * 16;
            unsigned int afr[4][4];
#pragma unroll
            for (int mt = 0; mt < 4; mt++) {
                ldsm4(afr[mt], ab + (unsigned int)((wm + mt * 16 + a_row_off) * PITCH
                                                   + kw + a_col_off) * 2u);
            }
            unsigned int bfr[8][2];
#pragma unroll
            for (int p = 0; p < 4; p++) {
                unsigned int tmp[4];
                ldsm4(tmp, bb + (unsigned int)((wn + p * 16 + b_row_off) * PITCH
                                               + kw + b_col_off) * 2u);
                bfr[2 * p][0] = tmp[0]; bfr[2 * p][1] = tmp[1];
                bfr[2 * p + 1][0] = tmp[2]; bfr[2 * p + 1][1] = tmp[3];
            }
#pragma unroll
            for (int mt = 0; mt < 4; mt++)
#pragma unroll
                for (int nt = 0; nt < 8; nt++) { mma16816(acc[mt][nt], afr[mt], bfr[nt]); }
        }
        __syncthreads();
    }

    // ---- epilogue: bias + leaky into smem e-tile ----
    float* et = (float*)sm;   // [128][EPITCH]
#pragma unroll
    for (int mt = 0; mt < 4; mt++) {
        const int r0 = wm + mt * 16 + g;
#pragma unroll
        for (int nt = 0; nt < 8; nt++) {
            const int cl = wn + nt * 8 + tig * 2;
            const float b0 = bias[n0 + cl], b1 = bias[n0 + cl + 1];
            float v00 = acc[mt][nt][0] + b0; v00 = (v00 >= 0.0f) ? v00 : 0.2f * v00;
            float v01 = acc[mt][nt][1] + b1; v01 = (v01 >= 0.0f) ? v01 : 0.2f * v01;
            float v10 = acc[mt][nt][2] + b0; v10 = (v10 >= 0.0f) ? v10 : 0.2f * v10;
            float v11 = acc[mt][nt][3] + b1; v11 = (v11 >= 0.0f) ? v11 : 0.2f * v11;
            et[r0 * EPITCH + cl] = v00;
            et[r0 * EPITCH + cl + 1] = v01;
            et[(r0 + 8) * EPITCH + cl] = v10;
            et[(r0 + 8) * EPITCH + cl + 1] = v11;
        }
    }
    __syncthreads();

    // ---- coalesced bf16-split write + per-column stats ----
    const int tx = tid & 15, ty = tid >> 4;   // tx: col group of 8; ty: 16 rows
    float ssum[8], ssq[8];
#pragma unroll
    for (int c = 0; c < 8; c++) { ssum[c] = 0.0f; ssq[c] = 0.0f; }
#pragma unroll
    for (int i = 0; i < 16; i++) {
        const int r = ty * 16 + i;
        const int m = m0 + r;
        float4 a = *(const float4*)&et[r * EPITCH + tx * 8];
        float4 b = *(const float4*)&et[r * EPITCH + tx * 8 + 4];
        float v[8];
        v[0] = a.x; v[1] = a.y; v[2] = a.z; v[3] = a.w;
        v[4] = b.x; v[5] = b.y; v[6] = b.z; v[7] = b.w;
        __nv_bfloat16 hh[8];
        __nv_bfloat16 ll[8];
#pragma unroll
        for (int c = 0; c < 8; c++) {
            ssum[c] += v[c]; ssq[c] += v[c] * v[c];
            bfsplit(v[c], hh[c], ll[c]);
        }
        *(uint4*)&d_ehi[(size_t)m * HID + n0 + tx * 8] = *(uint4*)hh;
        *(uint4*)&d_elo[(size_t)m * HID + n0 + tx * 8] = *(uint4*)ll;
    }
    __syncthreads();
    float* sb = et;   // overlay: [8][128]
#pragma unroll
    for (int c = 0; c < 8; c++) { sb[ty * 128 + tx * 8 + c] = ssum[c]; }
    __syncthreads();
    {
        float tot = 0.0f;
#pragma unroll
        for (int rr = 0; rr < 8; rr++) { tot += sb[rr * 128 + tid]; }
        atomicAdd(&d_sum[n0 + tid], tot);
    }
    __syncthreads();
#pragma unroll
    for (int c = 0; c < 8; c++) { sb[ty * 128 + tx * 8 + c] = ssq[c]; }
    __syncthreads();
    {
        float tot = 0.0f;
#pragma unroll
        for (int rr = 0; rr < 8; rr++) { tot += sb[rr * 128 + tid]; }
        atomicAdd(&d_sumsq[n0 + tid], tot);
    }
    __threadfence();
    __syncthreads();
    __shared__ int last;
    if (tid == 0) {
        int v = atomicAdd(&d_ctr, 1);
        last = (v == (int)(gridDim.x * gridDim.y) - 1) ? 1 : 0;
    }
    __syncthreads();
    if (last) {
        __threadfence();
        for (int h = tid; h < HID; h += 128) {
            float mean = d_sum[h] * (1.0f / 32768.0f);
            float var = d_sumsq[h] * (1.0f / 32768.0f) - mean * mean;
            var = var > 0.0f ? var : 0.0f;
            float sc = gamma[h] * rsqrtf(var + 1e-5f);
            d_scale[h] = sc;
            d_shift[h] = beta[h] - mean * sc;
        }
    }
}

// ---------------- k_prep: whh interleaved + gim + BN-folded W'/bias' -------
__global__ void k_prep(const float* __restrict__ wx, const float* __restrict__ wm,
                       const float* __restrict__ mem, const float* __restrict__ wim,
                       const float* __restrict__ bim,
                       const float* __restrict__ wih, const float* __restrict__ bih) {
    const int blk = blockIdx.x, tid = threadIdx.x;
    if (blk < 768) {
        const int idx = blk * 256 + tid;
        const int j = idx / OUTD, k = idx % OUTD;
        const int dst = ((k >> 1) * G3 + j) * 2 + (k & 1);
        d_whh2x[dst] = wx[idx];
        d_whh2m[dst] = wm[idx];
    } else if (blk < 896) {
        const int t = blk - 768;
        const float4* m4 = (const float4*)(mem + t * HID);
        for (int j = tid; j < G3; j += 256) {
            const float4* w4 = (const float4*)(wim + (size_t)j * HID);
            float acc = bim[j];
#pragma unroll 8
            for (int k = 0; k < HID / 4; k++) {
                float4 a = m4[k], b = w4[k];
                acc = fmaf(a.x, b.x, fmaf(a.y, b.y, fmaf(a.z, b.z, fmaf(a.w, b.w, acc))));
            }
            d_gim[t * G3 + j] = acc;
        }
    } else {
        const int j = blk - 896;
        const float* wr = wih + (size_t)j * HID;
        const int h0 = tid * 4;
        float4 w4 = *(const float4*)&wr[h0];
        float4 sc = *(const float4*)&d_scale[h0];
        float4 sh = *(const float4*)&d_shift[h0];
        float wv[4];
        wv[0] = w4.x * sc.x; wv[1] = w4.y * sc.y;
        wv[2] = w4.z * sc.z; wv[3] = w4.w * sc.w;
        float dot = w4.x * sh.x + w4.y * sh.y + w4.z * sh.z + w4.w * sh.w;
        __nv_bfloat16 hh[4];
        __nv_bfloat16 ll[4];
#pragma unroll
        for (int q = 0; q < 4; q++) { bfsplit(wv[q], hh[q], ll[q]); }
        *(ull*)&d_whi[(size_t)j * HID + h0] = *(ull*)hh;
        *(ull*)&d_wlo[(size_t)j * HID + h0] = *(ull*)ll;
        __shared__ float red[256];
        red[tid] = dot;
        __syncthreads();
        for (int s = 128; s > 0; s >>= 1) {
            if (tid < s) { red[tid] += red[tid + s]; }
            __syncthreads();
        }
        if (tid == 0) { d_bip[j] = bih[j] + red[0]; }
    }
}

// ---------------- k_gemm_mma: gi = split-bf16 HMMA GEMM + bias' ------------
__global__ void __launch_bounds__(128, 2)
k_gemm_mma(const float* __restrict__ bias) {
    extern __shared__ __nv_bfloat16 sm[];
    const int tid = threadIdx.x;
    const int wid = tid >> 5, lane = tid & 31;
    const int m0 = blockIdx.x * 128, n0 = blockIdx.y * 128;
    const int wm = (wid >> 1) * 64, wn = (wid & 1) * 64;
    const int g = lane >> 2, tig = lane & 3;
    const unsigned int sbase = smem_to_u32(sm);

    const int a_row_off = (lane & 7) + ((lane >> 3) & 1) * 8;
    const int a_col_off = (lane >> 4) * 8;
    const int b_row_off = (lane & 7) + (lane >> 4) * 8;
    const int b_col_off = ((lane >> 3) & 1) * 8;

    float acc[4][8][4];
#pragma unroll
    for (int mt = 0; mt < 4; mt++)
#pragma unroll
        for (int nt = 0; nt < 8; nt++)
#pragma unroll
            for (int r = 0; r < 4; r++) { acc[mt][nt][r] = 0.0f; }

    auto stage = [&](int c, int buf) {
        const __nv_bfloat16* Ap = (c < 32) ? d_ehi : d_elo;
        const __nv_bfloat16* Bp = (c < 16) ? d_whi : ((c < 32) ? d_wlo : d_whi);
        const int kk = (c & 15) * 64;
        const unsigned int ab = sbase + (unsigned int)(buf * 2 * BUFE) * 2u;
        const unsigned int bb = ab + (unsigned int)BUFE * 2u;
#pragma unroll
        for (int it = 0; it < 8; it++) {
            const int idx = tid + it * 128;
            const int row = idx >> 3;
            const int col = (idx & 7) * 8;
            cpasync16(ab + (unsigned int)(row * PITCH + col) * 2u,
                      Ap + (size_t)(m0 + row) * HID + kk + col);
            cpasync16(bb + (unsigned int)(row * PITCH + col) * 2u,
                      Bp + (size_t)(n0 + row) * HID + kk + col);
        }
        CP_COMMIT();
    };

    stage(0, 0);
    for (int c = 0; c < 48; c++) {
        const int buf = c & 1;
        if (c + 1 < 48) {
            stage(c + 1, 1 - buf);
            CP_WAIT(1);
        } else {
            CP_WAIT(0);
        }
        __syncthreads();
        const unsigned int ab = sbase + (unsigned int)(buf * 2 * BUFE) * 2u;
        const unsigned int bb = ab + (unsigned int)BUFE * 2u;
#pragma unroll
        for (int ks = 0; ks < 4; ks++) {
            const int kw = ks * 16;
            unsigned int afr[4][4];
#pragma unroll
            for (int mt = 0; mt < 4; mt++) {
                ldsm4(afr[mt], ab + (unsigned int)((wm + mt * 16 + a_row_off) * PITCH
                                                   + kw + a_col_off) * 2u);
            }
            unsigned int bfr[8][2];
#pragma unroll
            for (int p = 0; p < 4; p++) {
                unsigned int tmp[4];
                ldsm4(tmp, bb + (unsigned int)((wn + p * 16 + b_row_off) * PITCH
                                               + kw + b_col_off) * 2u);
                bfr[2 * p][0] = tmp[0]; bfr[2 * p][1] = tmp[1];
                bfr[2 * p + 1][0] = tmp[2]; bfr[2 * p + 1][1] = tmp[3];
            }
#pragma unroll
            for (int mt = 0; mt < 4; mt++)
#pragma unroll
                for (int nt = 0; nt < 8; nt++) { mma16816(acc[mt][nt], afr[mt], bfr[nt]); }
        }
        __syncthreads();
    }

#pragma unroll
    for (int mt = 0; mt < 4; mt++) {
        const int row = m0 + wm + mt * 16 + g;
#pragma unroll
        for (int nt = 0; nt < 8; nt++) {
            const int col = n0 + wn + nt * 8 + tig * 2;
            const float b0 = bias[col], b1 = bias[col + 1];
            float2 v0, v1;
            v0.x = acc[mt][nt][0] + b0; v0.y = acc[mt][nt][1] + b1;
            v1.x = acc[mt][nt][2] + b0; v1.y = acc[mt][nt][3] + b1;
            *(float2*)&d_gi[(size_t)row * G3 + col] = v0;
            *(float2*)&d_gi[(size_t)(row + 8) * G3 + col] = v1;
        }
    }
}

// ---------------- k_scan: persistent GRU recurrences (R13 winner) ----------
__global__ void __launch_bounds__(384, 1)
k_scan(const float* __restrict__ bhhx, const float* __restrict__ bhhm) {
    __shared__ ull h2a[2][OUTD];
    __shared__ ull gh2s[2][G3];
    __shared__ float hm_s[OUTD];
    __shared__ float ghm_s[G3];
    const int tid = threadIdx.x;
    const int j0 = 2 * tid;

    if (blockIdx.x < 64) {
        const int bb = blockIdx.x * 4;
        for (int i = tid; i < 2 * OUTD; i += 384) { ((ull*)h2a)[i] = 0ull; }
        const float2 bh2 = *(const float2*)&bhhx[j0];
        const ull bj0 = pk2(bh2.x, bh2.x);
        const ull bj1 = pk2(bh2.y, bh2.y);
        const int p0 = tid >> 8, dd0 = tid & 255;
        const int dd1 = 128 + tid;
        __syncthreads();
        for (int t = 0; t < TST; t++) {
            float g0r0, g0z0, g0n0, g0r1, g0z1, g0n1;
            {
                const float* giA = &d_gi[((size_t)(bb + 2 * p0) * TST + t) * G3];
                const float* giB = &d_gi[((size_t)(bb + 2 * p0 + 1) * TST + t) * G3];
                g0r0 = giA[dd0]; g0z0 = giA[OUTD + dd0]; g0n0 = giA[2 * OUTD + dd0];
                g0r1 = giB[dd0]; g0z1 = giB[OUTD + dd0]; g0n1 = giB[2 * OUTD + dd0];
            }
            float g1r0 = 0, g1z0 = 0, g1n0 = 0, g1r1 = 0, g1z1 = 0, g1n1 = 0;
            if (tid < 128) {
                const float* giA = &d_gi[((size_t)(bb + 2) * TST + t) * G3];
                const float* giB = &d_gi[((size_t)(bb + 3) * TST + t) * G3];
                g1r0 = giA[dd1]; g1z0 = giA[OUTD + dd1]; g1n0 = giA[2 * OUTD + dd1];
                g1r1 = giB[dd1]; g1z1 = giB[OUTD + dd1]; g1n1 = giB[2 * OUTD + dd1];
            }
            ull a00 = bj0, a01 = bj0, a10 = bj1, a11 = bj1;
#pragma unroll 16
            for (int k2 = 0; k2 < OUTD / 2; k2++) {
                const float4 w4 = *(const float4*)&d_whh2x[(k2 * G3 + j0) * 2];
                const ulonglong2 hp0 = *(const ulonglong2*)&h2a[0][2 * k2];
                const ulonglong2 hp1 = *(const ulonglong2*)&h2a[1][2 * k2];
                ull wd;
                wd = pk2(w4.x, w4.x); fma2(a00, hp0.x, wd); fma2(a01, hp1.x, wd);
                wd = pk2(w4.y, w4.y); fma2(a00, hp0.y, wd); fma2(a01, hp1.y, wd);
                wd = pk2(w4.z, w4.z); fma2(a10, hp0.x, wd); fma2(a11, hp1.x, wd);
                wd = pk2(w4.w, w4.w); fma2(a10, hp0.y, wd); fma2(a11, hp1.y, wd);
            }
            gh2s[0][j0] = a00; gh2s[0][j0 + 1] = a10;
            gh2s[1][j0] = a01; gh2s[1][j0 + 1] = a11;
            __syncthreads();
            {
                float2 ghr = upk2(gh2s[p0][dd0]);
                float2 ghz = upk2(gh2s[p0][OUTD + dd0]);
                float2 ghn = upk2(gh2s[p0][2 * OUTD + dd0]);
                float2 hold = upk2(h2a[p0][dd0]);
                float r0 = fsig(g0r0 + ghr.x), r1 = fsig(g0r1 + ghr.y);
                float z0 = fsig(g0z0 + ghz.x), z1 = fsig(g0z1 + ghz.y);
                float n0 = ftanh(g0n0 + r0 * ghn.x), n1 = ftanh(g0n1 + r1 * ghn.y);
                h2a[p0][dd0] = pk2((1.0f - z0) * n0 + z0 * hold.x,
                                   (1.0f - z1) * n1 + z1 * hold.y);
            }
            if (tid < 128) {
                float2 ghr = upk2(gh2s[1][dd1]);
                float2 ghz = upk2(gh2s[1][OUTD + dd1]);
                float2 ghn = upk2(gh2s[1][2 * OUTD + dd1]);
                float2 hold = upk2(h2a[1][dd1]);
                float r0 = fsig(g1r0 + ghr.x), r1 = fsig(g1r1 + ghr.y);
                float z0 = fsig(g1z0 + ghz.x), z1 = fsig(g1z1 + ghz.y);
                float n0 = ftanh(g1n0 + r0 * ghn.x), n1 = ftanh(g1n1 + r1 * ghn.y);
                h2a[1][dd1] = pk2((1.0f - z0) * n0 + z0 * hold.x,
                                  (1.0f - z1) * n1 + z1 * hold.y);
            }
            __syncthreads();
        }
        for (int d = tid; d < OUTD; d += 384) {
#pragma unroll
            for (int p = 0; p < 2; p++) {
                float2 h = upk2(h2a[p][d]);
                d_hxf[(bb + 2 * p) * OUTD + d] = h.x;
                d_hxf[(bb + 2 * p + 1) * OUTD + d] = h.y;
            }
        }
    } else {
        for (int i = tid; i < OUTD; i += 384) { hm_s[i] = 0.0f; }
        const float2 bh2 = *(const float2*)&bhhm[j0];
        __syncthreads();
        for (int t = 0; t < TST; t++) {
            float grv = 0, gzv = 0, gnv = 0;
            if (tid < OUTD) {
                const float* gi = &d_gim[t * G3];
                grv = gi[tid]; gzv = gi[OUTD + tid]; gnv = gi[2 * OUTD + tid];
            }
            float a0 = bh2.x, a1 = bh2.y;
#pragma unroll 16
            for (int k2 = 0; k2 < OUTD / 2; k2++) {
                const float4 w4 = *(const float4*)&d_whh2m[(k2 * G3 + j0) * 2];
                const float2 h2 = *(const float2*)&hm_s[2 * k2];
                a0 = fmaf(h2.x, w4.x, fmaf(h2.y, w4.y, a0));
                a1 = fmaf(h2.x, w4.z, fmaf(h2.y, w4.w, a1));
            }
            ghm_s[j0] = a0; ghm_s[j0 + 1] = a1;
            __syncthreads();
            if (tid < OUTD) {
                float rr = fsig(grv + ghm_s[tid]);
                float zz = fsig(gzv + ghm_s[OUTD + tid]);
                float nn = ftanh(gnv + rr * ghm_s[2 * OUTD + tid]);
                hm_s[tid] = (1.0f - zz) * nn + zz * hm_s[tid];
            }
            __syncthreads();
        }
        for (int d = tid; d < OUTD; d += 384) { d_hmf[d] = hm_s[d]; }
    }
}

// ---------------- k_final: cosine gate + blend + stat cleanup --------------
__global__ void k_final(const float* __restrict__ Wsx, const float* __restrict__ bsx,
                        const float* __restrict__ Wsm, const float* __restrict__ bsm,
                        float* __restrict__ out) {
    const int b = blockIdx.x, lane = threadIdx.x;
    const int gidx = b * 32 + lane;
    if (gidx < HID) { d_sum[gidx] = 0.0f; d_sumsq[gidx] = 0.0f; }
    if (gidx == 0) { d_ctr = 0; }

    float hx[8], hm[8];
#pragma unroll
    for (int i = 0; i < 8; i++) {
        hx[i] = d_hxf[b * OUTD + lane * 8 + i];
        hm[i] = d_hmf[lane * 8 + i];
    }
    float qx[4], qm[4];
#pragma unroll
    for (int s = 0; s < 4; s++) {
        float ax = 0.0f, am = 0.0f;
#pragma unroll
        for (int i = 0; i < 8; i++) {
            ax = fmaf(hx[i], Wsx[s * OUTD + lane * 8 + i], ax);
            am = fmaf(hm[i], Wsm[s * OUTD + lane * 8 + i], am);
        }
        for (int off = 16; off; off >>= 1) {
            ax += __shfl_xor_sync(0xFFFFFFFFu, ax, off);
            am += __shfl_xor_sync(0xFFFFFFFFu, am, off);
        }
        qx[s] = ax + bsx[s];
        qm[s] = am + bsm[s];
    }
    float num = 0.0f, nx = 0.0f, nm = 0.0f;
#pragma unroll
    for (int s = 0; s < 4; s++) {
        num = fmaf(qx[s], qm[s], num);
        nx = fmaf(qx[s], qx[s], nx);
        nm = fmaf(qm[s], qm[s], nm);
    }
    float den = fmaxf(sqrtf(nx), 1e-8f) * fmaxf(sqrtf(nm), 1e-8f);
    float gg = 1.0f / (1.0f + expf(-num / den));
#pragma unroll
    for (int i = 0; i < 8; i++) {
        out[b * OUTD + lane * 8 + i] = gg * hx[i] + (1.0f - gg) * hm[i];
    }
}

// ---------------- launcher -------------------------------------------------
// Launch #4 = k_gemm_mma (ncu-profiled slot).
extern "C" void kernel_launch(void* const* d_in, const int* in_sizes, int n_in,
                              void* d_out, int out_size) {
    const float* x      = (const float*)d_in[0];
    const float* W_emb  = (const float*)d_in[1];
    const float* b_emb  = (const float*)d_in[2];
    const float* gamma  = (const float*)d_in[3];
    const float* beta   = (const float*)d_in[4];
    const float* memory = (const float*)d_in[5];
    const float* w_ih_x = (const float*)d_in[6];
    const float* w_hh_x = (const float*)d_in[7];
    const float* b_ih_x = (const float*)d_in[8];
    const float* b_hh_x = (const float*)d_in[9];
    const float* w_ih_m = (const float*)d_in[10];
    const float* w_hh_m = (const float*)d_in[11];
    const float* b_ih_m = (const float*)d_in[12];
    const float* b_hh_m = (const float*)d_in[13];
    const float* W_sx   = (const float*)d_in[14];
    const float* b_sx   = (const float*)d_in[15];
    const float* W_sm   = (const float*)d_in[16];
    const float* b_sm   = (const float*)d_in[17];
    float* out = (float*)d_out;

    float* bip = nullptr; cudaGetSymbolAddress((void**)&bip, d_bip);

    const int smem_mma = 2 * 2 * BUFE * (int)sizeof(__nv_bfloat16);  // 73728 B
    static int attr_set = 0;
    if (!attr_set) {
        cudaFuncSetAttribute(k_gemm_mma, cudaFuncAttributeMaxDynamicSharedMemorySize,
                             smem_mma);
        cudaFuncSetAttribute(k_embed_mma, cudaFuncAttributeMaxDynamicSharedMemorySize,
                             smem_mma);
        attr_set = 1;
    }

    // 1: bf16 hi/lo split of x and W_emb
    k_xsplit<<<2112, 256>>>(x, W_emb);
    // 2: embed HMMA GEMM + leaky + raw-e bf16 split + BN stats + finalize
    k_embed_mma<<<dim3(256, 8), 128, smem_mma>>>(b_emb, gamma, beta);
    // 3: prep (whh interleaved + gim + BN-folded W' split + bias')
    k_prep<<<1664, 256>>>(w_hh_x, w_hh_m, memory, w_ih_m, b_ih_m, w_ih_x, b_ih_x);
    // 4: HMMA gi GEMM (ncu-profiled slot)
    k_gemm_mma<<<dim3(256, 6), 128, smem_mma>>>(bip);
    // 5: recurrences
    k_scan<<<65, 384>>>(b_hh_x, b_hh_m);
    // 6: gate + blend + stat cleanup
    k_final<<<256, 32>>>(W_sx, b_sx, W_sm, b_sm, out);
}